// round 1
// baseline (speedup 1.0000x reference)
#include <cuda_runtime.h>
#include <cstdint>

// Problem constants
#define B_    16
#define CIN_  64
#define H_    128
#define W_    128
#define COUT_ 128
#define NPIX  (H_ * W_)          // 16384
#define NMAPS (B_ * CIN_)        // 1024
#define NAN_CNT_THRESH 4608      // counts >= 0.5 * (16*64*3*3)

// Conv tiling
#define TOH   8
#define TOW   32
#define TCO   64
#define CCH   8
#define XROWS (TOH + 2)          // 10
#define XUSED (TOW + 2)          // 34
#define XCOLS 36                 // padded

// Scratch (device globals: allocation-free per harness rules)
__device__ int           g_msum[NPIX];
__device__ unsigned char g_flag[NPIX];

// ---------------------------------------------------------------------------
// Kernel 1: zero the per-pixel NaN counter
// ---------------------------------------------------------------------------
__global__ void nanconv_init_kernel() {
    int i = blockIdx.x * blockDim.x + threadIdx.x;
    if (i < NPIX) g_msum[i] = 0;
}

// ---------------------------------------------------------------------------
// Kernel 2: count NaNs per (h,w) pixel across all (b, cin) maps.
// grid = (NPIX/256, 16). Each thread sums 64 maps for one pixel, then does a
// single atomicAdd (addresses fully spread across threads -> near REDG rate).
// ---------------------------------------------------------------------------
__global__ void nanconv_count_kernel(const float* __restrict__ img) {
    int p  = blockIdx.x * 256 + threadIdx.x;      // pixel id
    int m0 = blockIdx.y * 64;                     // map chunk base
    const float* base = img + (size_t)m0 * NPIX + p;
    int cnt = 0;
#pragma unroll 8
    for (int m = 0; m < 64; m++) {
        float v = base[(size_t)m * NPIX];
        cnt += (v != v);
    }
    if (cnt) atomicAdd(&g_msum[p], cnt);
}

// ---------------------------------------------------------------------------
// Kernel 3: 3x3 box-sum of g_msum (zero padding) -> threshold flag
// ---------------------------------------------------------------------------
__global__ void nanconv_flag_kernel() {
    int p = blockIdx.x * 256 + threadIdx.x;
    if (p >= NPIX) return;
    int oh = p >> 7;
    int ow = p & 127;
    int s = 0;
#pragma unroll
    for (int dh = -1; dh <= 1; dh++) {
#pragma unroll
        for (int dw = -1; dw <= 1; dw++) {
            int hh = oh + dh, ww = ow + dw;
            if ((unsigned)hh < H_ && (unsigned)ww < W_)
                s += g_msum[hh * W_ + ww];
        }
    }
    g_flag[p] = (s >= NAN_CNT_THRESH) ? 1 : 0;
}

// ---------------------------------------------------------------------------
// Kernel 4: direct tiled conv, fp32.
// Block: 256 threads. blockIdx = (spatial tile [64], cout block [2], batch [16]).
// Thread micro-tile: 8 couts (strided by 8) x 8 pixels (contiguous ow octet).
// Input + weights staged in smem per cin-chunk of 8; NaN->0 on the way in.
// ---------------------------------------------------------------------------
__global__ __launch_bounds__(256)
void nanconv_conv_kernel(const float* __restrict__ img,
                         const float* __restrict__ wgt,
                         const float* __restrict__ bias,
                         float* __restrict__ out)
{
    __shared__ float x_s[CCH][XROWS][XCOLS];   // 11.25 KB
    __shared__ float w_s[CCH][9][TCO];         // 18   KB

    const int tid = threadIdx.x;
    const int cl  = tid & 7;        // cout lane 0..7
    const int pl  = tid >> 3;       // pixel lane 0..31
    const int ohl = pl >> 2;        // local output row 0..7
    const int g   = pl & 3;         // ow octet 0..3

    const int tile = blockIdx.x;                 // 0..63
    const int oh0  = (tile >> 2) * TOH;          // 16 oh tiles
    const int ow0  = (tile & 3)  * TOW;          // 4 ow tiles
    const int cb   = blockIdx.y;                 // cout block 0..1
    const int b    = blockIdx.z;                 // batch

    float acc[8][8];
#pragma unroll
    for (int i = 0; i < 8; i++)
#pragma unroll
        for (int j = 0; j < 8; j++) acc[i][j] = 0.f;

    for (int cc = 0; cc < CIN_; cc += CCH) {
        // ---- stage input halo tile (NaN->0, zero padding) ----
        for (int e = tid; e < CCH * XROWS * XUSED; e += 256) {
            int c = e / (XROWS * XUSED);
            int r = (e / XUSED) % XROWS;
            int w = e % XUSED;
            int hh = oh0 - 1 + r;
            int ww = ow0 - 1 + w;
            float v = 0.f;
            if ((unsigned)hh < H_ && (unsigned)ww < W_) {
                v = img[(((size_t)b * CIN_ + cc + c) * H_ + hh) * W_ + ww];
                if (v != v) v = 0.f;   // nan_to_num
            }
            x_s[c][r][w] = v;
        }
        // ---- stage weights re-laid-out as [cin][k][cout] ----
        for (int e = tid; e < CCH * 9 * TCO; e += 256) {
            int c  = e / (9 * TCO);
            int k  = (e / TCO) % 9;
            int co = e % TCO;
            w_s[c][k][co] = wgt[(((size_t)(cb * TCO + co)) * CIN_ + cc + c) * 9 + k];
        }
        __syncthreads();

        // ---- compute: 8 cin x 3 kh x (10 x-loads, 3 kw x 8 w-loads, 192 FMA) ----
#pragma unroll
        for (int c = 0; c < CCH; c++) {
#pragma unroll
            for (int kh = 0; kh < 3; kh++) {
                float xr[10];
#pragma unroll
                for (int t = 0; t < 10; t++)
                    xr[t] = x_s[c][ohl + kh][g * 8 + t];
#pragma unroll
                for (int kw = 0; kw < 3; kw++) {
                    float wr[8];
#pragma unroll
                    for (int i = 0; i < 8; i++)
                        wr[i] = w_s[c][kh * 3 + kw][cl + 8 * i];
#pragma unroll
                    for (int i = 0; i < 8; i++)
#pragma unroll
                        for (int j = 0; j < 8; j++)
                            acc[i][j] += wr[i] * xr[kw + j];
                }
            }
        }
        __syncthreads();
    }

    // ---- epilogue: NaN flag + bias, write out ----
    const int oh = oh0 + ohl;
    unsigned char fl[8];
#pragma unroll
    for (int j = 0; j < 8; j++)
        fl[j] = g_flag[oh * W_ + ow0 + g * 8 + j];

    const float nanv = __int_as_float(0x7fc00000);
#pragma unroll
    for (int i = 0; i < 8; i++) {
        int co = cb * TCO + cl + 8 * i;
        float bs = bias[co];
        size_t obase = (((size_t)b * COUT_ + co) * H_ + oh) * W_ + ow0 + (size_t)g * 8;
#pragma unroll
        for (int j = 0; j < 8; j++)
            out[obase + j] = fl[j] ? nanv : (acc[i][j] + bs);
    }
}

// ---------------------------------------------------------------------------
// Launch
// ---------------------------------------------------------------------------
extern "C" void kernel_launch(void* const* d_in, const int* in_sizes, int n_in,
                              void* d_out, int out_size)
{
    (void)in_sizes; (void)n_in; (void)out_size;
    const float* img  = (const float*)d_in[0];   // [16,64,128,128]
    const float* wgt  = (const float*)d_in[1];   // [128,64,3,3]
    const float* bias = (const float*)d_in[2];   // [128]
    float* out = (float*)d_out;                  // [16,128,128,128]

    nanconv_init_kernel<<<NPIX / 256, 256>>>();
    nanconv_count_kernel<<<dim3(NPIX / 256, NMAPS / 64), 256>>>(img);
    nanconv_flag_kernel<<<NPIX / 256, 256>>>();
    nanconv_conv_kernel<<<dim3(64, 2, 16), 256>>>(img, wgt, bias, out);
}

// round 3
// speedup vs baseline: 1.0045x; 1.0045x over previous
#include <cuda_runtime.h>
#include <cstdint>

// Problem constants
#define B_    16
#define CIN_  64
#define H_    128
#define W_    128
#define COUT_ 128
#define NPIX  (H_ * W_)          // 16384
#define NMAPS (B_ * CIN_)        // 1024
#define NAN_CNT_THRESH 4608      // counts >= 0.5 * (16*64*3*3)

// Conv tiling
#define TOH   8
#define TOW   32
#define TCO   64
#define CCH   8
#define XROWS (TOH + 2)          // 10
#define XUSED (TOW + 2)          // 34
#define XCOLS 36                 // padded

// Scratch (device globals: allocation-free per harness rules)
__device__ int           g_msum[NPIX];
__device__ unsigned char g_flag[NPIX];

// ---------------------------------------------------------------------------
// Kernel 1: zero the per-pixel NaN counter
// ---------------------------------------------------------------------------
__global__ void nanconv_init_kernel() {
    int i = blockIdx.x * blockDim.x + threadIdx.x;
    if (i < NPIX) g_msum[i] = 0;
}

// ---------------------------------------------------------------------------
// Kernel 2: count NaNs per (h,w) pixel across all (b, cin) maps.
// grid = (NPIX/256, 16). Each thread sums 64 maps for one pixel, then does a
// single atomicAdd (addresses fully spread across threads -> near REDG rate).
// ---------------------------------------------------------------------------
__global__ void nanconv_count_kernel(const float* __restrict__ img) {
    int p  = blockIdx.x * 256 + threadIdx.x;      // pixel id
    int m0 = blockIdx.y * 64;                     // map chunk base
    const float* base = img + (size_t)m0 * NPIX + p;
    int cnt = 0;
#pragma unroll 8
    for (int m = 0; m < 64; m++) {
        float v = base[(size_t)m * NPIX];
        cnt += (v != v);
    }
    if (cnt) atomicAdd(&g_msum[p], cnt);
}

// ---------------------------------------------------------------------------
// Kernel 3: 3x3 box-sum of g_msum (zero padding) -> threshold flag
// ---------------------------------------------------------------------------
__global__ void nanconv_flag_kernel() {
    int p = blockIdx.x * 256 + threadIdx.x;
    if (p >= NPIX) return;
    int oh = p >> 7;
    int ow = p & 127;
    int s = 0;
#pragma unroll
    for (int dh = -1; dh <= 1; dh++) {
#pragma unroll
        for (int dw = -1; dw <= 1; dw++) {
            int hh = oh + dh, ww = ow + dw;
            if ((unsigned)hh < H_ && (unsigned)ww < W_)
                s += g_msum[hh * W_ + ww];
        }
    }
    g_flag[p] = (s >= NAN_CNT_THRESH) ? 1 : 0;
}

// ---------------------------------------------------------------------------
// Kernel 4: direct tiled conv, fp32.
// Block: 256 threads. blockIdx = (spatial tile [64], cout block [2], batch [16]).
// Thread micro-tile: 8 couts (strided by 8) x 8 pixels (contiguous ow octet).
// Input + weights staged in smem per cin-chunk of 8; NaN->0 on the way in.
// ---------------------------------------------------------------------------
__global__ __launch_bounds__(256)
void nanconv_conv_kernel(const float* __restrict__ img,
                         const float* __restrict__ wgt,
                         const float* __restrict__ bias,
                         float* __restrict__ out)
{
    __shared__ float x_s[CCH][XROWS][XCOLS];   // 11.25 KB
    __shared__ float w_s[CCH][9][TCO];         // 18   KB

    const int tid = threadIdx.x;
    const int cl  = tid & 7;        // cout lane 0..7
    const int pl  = tid >> 3;       // pixel lane 0..31
    const int ohl = pl >> 2;        // local output row 0..7
    const int g   = pl & 3;         // ow octet 0..3

    const int tile = blockIdx.x;                 // 0..63
    const int oh0  = (tile >> 2) * TOH;          // 16 oh tiles
    const int ow0  = (tile & 3)  * TOW;          // 4 ow tiles
    const int cb   = blockIdx.y;                 // cout block 0..1
    const int b    = blockIdx.z;                 // batch

    float acc[8][8];
#pragma unroll
    for (int i = 0; i < 8; i++)
#pragma unroll
        for (int j = 0; j < 8; j++) acc[i][j] = 0.f;

    for (int cc = 0; cc < CIN_; cc += CCH) {
        // ---- stage input halo tile (NaN->0, zero padding) ----
        for (int e = tid; e < CCH * XROWS * XUSED; e += 256) {
            int c = e / (XROWS * XUSED);
            int r = (e / XUSED) % XROWS;
            int w = e % XUSED;
            int hh = oh0 - 1 + r;
            int ww = ow0 - 1 + w;
            float v = 0.f;
            if ((unsigned)hh < H_ && (unsigned)ww < W_) {
                v = img[(((size_t)b * CIN_ + cc + c) * H_ + hh) * W_ + ww];
                if (v != v) v = 0.f;   // nan_to_num
            }
            x_s[c][r][w] = v;
        }
        // ---- stage weights re-laid-out as [cin][k][cout] ----
        for (int e = tid; e < CCH * 9 * TCO; e += 256) {
            int c  = e / (9 * TCO);
            int k  = (e / TCO) % 9;
            int co = e % TCO;
            w_s[c][k][co] = wgt[(((size_t)(cb * TCO + co)) * CIN_ + cc + c) * 9 + k];
        }
        __syncthreads();

        // ---- compute: 8 cin x 3 kh x (10 x-loads, 3 kw x 8 w-loads, 192 FMA) ----
#pragma unroll
        for (int c = 0; c < CCH; c++) {
#pragma unroll
            for (int kh = 0; kh < 3; kh++) {
                float xr[10];
#pragma unroll
                for (int t = 0; t < 10; t++)
                    xr[t] = x_s[c][ohl + kh][g * 8 + t];
#pragma unroll
                for (int kw = 0; kw < 3; kw++) {
                    float wr[8];
#pragma unroll
                    for (int i = 0; i < 8; i++)
                        wr[i] = w_s[c][kh * 3 + kw][cl + 8 * i];
#pragma unroll
                    for (int i = 0; i < 8; i++)
#pragma unroll
                        for (int j = 0; j < 8; j++)
                            acc[i][j] += wr[i] * xr[kw + j];
                }
            }
        }
        __syncthreads();
    }

    // ---- epilogue: NaN flag + bias, write out ----
    const int oh = oh0 + ohl;
    unsigned char fl[8];
#pragma unroll
    for (int j = 0; j < 8; j++)
        fl[j] = g_flag[oh * W_ + ow0 + g * 8 + j];

    const float nanv = __int_as_float(0x7fc00000);
#pragma unroll
    for (int i = 0; i < 8; i++) {
        int co = cb * TCO + cl + 8 * i;
        float bs = bias[co];
        size_t obase = (((size_t)b * COUT_ + co) * H_ + oh) * W_ + ow0 + (size_t)g * 8;
#pragma unroll
        for (int j = 0; j < 8; j++)
            out[obase + j] = fl[j] ? nanv : (acc[i][j] + bs);
    }
}

// ---------------------------------------------------------------------------
// Launch
// ---------------------------------------------------------------------------
extern "C" void kernel_launch(void* const* d_in, const int* in_sizes, int n_in,
                              void* d_out, int out_size)
{
    (void)in_sizes; (void)n_in; (void)out_size;
    const float* img  = (const float*)d_in[0];   // [16,64,128,128]
    const float* wgt  = (const float*)d_in[1];   // [128,64,3,3]
    const float* bias = (const float*)d_in[2];   // [128]
    float* out = (float*)d_out;                  // [16,128,128,128]

    nanconv_init_kernel<<<NPIX / 256, 256>>>();
    nanconv_count_kernel<<<dim3(NPIX / 256, NMAPS / 64), 256>>>(img);
    nanconv_flag_kernel<<<NPIX / 256, 256>>>();
    nanconv_conv_kernel<<<dim3(64, 2, 16), 256>>>(img, wgt, bias, out);
}